// round 7
// baseline (speedup 1.0000x reference)
#include <cuda_runtime.h>
#include <cstdint>

#define BB 8
#define CC 32
#define FF 8
#define HH 128
#define WW 128
#define IHP 129
#define IWP 132                        // padded row stride (floats), 528 B
typedef unsigned long long ull;

// smem layout (floats):
#define T_OFF (IHP*IWP)                // 17028 : T table, 1024 float4
#define D_OFF (T_OFF + 4096)           // 21124 : D buffers 16 warps * 264 f
#define SMEM_FLOATS (D_OFF + 16*264)   // 25348 floats = 101392 B

__device__ __forceinline__ ull pk2(float lo, float hi) {
    ull r; asm("mov.b64 %0, {%1, %2};" : "=l"(r) : "f"(lo), "f"(hi)); return r;
}
__device__ __forceinline__ ull ffma2(ull a, ull b, ull c) {
    ull r; asm("fma.rn.f32x2 %0, %1, %2, %3;" : "=l"(r) : "l"(a), "l"(b), "l"(c));
    return r;
}
__device__ __forceinline__ uint32_t smem_u32(const void* p) {
    uint32_t a;
    asm("{ .reg .u64 t; cvta.to.shared.u64 t, %1; cvt.u32.u64 %0, t; }"
        : "=r"(a) : "l"(p));
    return a;
}

// ---------------------------------------------------------------------------
// Fused: one block per bc. Build integral + T table, then 16 warps = (f, half)
// each produce 64 output rows. Branch-free rolling window.
// ---------------------------------------------------------------------------
__global__ void __launch_bounds__(512, 2) boxconv_fused(
    const float* __restrict__ in,
    const float* __restrict__ xmn, const float* __restrict__ xmx,
    const float* __restrict__ ymn, const float* __restrict__ ymx,
    float* __restrict__ out)
{
    extern __shared__ float sm[];
    float*  I = sm;                                 // [IHP][IWP]
    float4* T = (float4*)(sm + T_OFF);              // [FF*HH]
    float*  O = sm + D_OFF;                         // build stripe offsets (reuse)

    const int bc   = blockIdx.x;
    const int c    = bc % CC;
    const int tid  = threadIdx.x;
    const int wid  = tid >> 5;
    const int lane = tid & 31;

    // ---- T table: per (f,h) row byte-offsets + fractional weights ----------
    for (int e = tid; e < FF * HH; e += 512) {
        int fi = e >> 7, h = e & 127;
        int cfi = c * FF + fi;
        float xm = xmn[cfi] * 128.0f;
        float xM = xmx[cfi] * 128.0f;
        float u0 = fminf(fmaxf((float)h + xm, 0.0f), 128.0f);
        float u1 = fminf(fmaxf((float)h + xM + 1.0f, 0.0f), 128.0f);
        int i0 = min(max(h + (int)floorf(xm), 0), 127);
        int i1 = min(max(h + (int)floorf(xM + 1.0f), 0), 127);
        float4 t;
        t.x = __int_as_float(i0 * (IWP * 4));
        t.y = __int_as_float(i1 * (IWP * 4));
        t.z = u0 - (float)i0;
        t.w = u1 - (float)i1;
        T[e] = t;
    }

    // ---- Build I: row scans (warp wid -> rows 8w..8w+7) --------------------
    if (tid < IWP) I[tid] = 0.0f;
    const float* img = in + (size_t)bc * (HH * WW);
#pragma unroll
    for (int r = 0; r < 8; ++r) {
        int row = wid * 8 + r;
        float4 cv = *(const float4*)(img + (size_t)row * WW + 4 * lane);
        float s4 = cv.x + cv.y + cv.z + cv.w;
        float x = __shfl_up_sync(0xffffffffu, s4, 1);
        if (lane == 0) x = 0.0f;
#pragma unroll
        for (int off = 1; off < 32; off <<= 1) {
            float t = __shfl_up_sync(0xffffffffu, x, off);
            if (lane >= off) x += t;
        }
        float4 o;
        o.x = x;
        o.y = x + cv.x;
        o.z = o.y + cv.y;
        o.w = o.z + cv.z;
        float* dst = I + (size_t)(row + 1) * IWP;
        *(float4*)(dst + 4 * lane) = o;
        if (lane == 31) {
            dst[128] = o.w + cv.w;
            dst[129] = 0.0f; dst[130] = 0.0f; dst[131] = 0.0f;
        }
    }
    __syncthreads();

    // level 1: within-stripe inclusive sums (8-row stripes)
    for (int g = lane; g < 33; g += 32) {
        float* col = I + 4 * g + (size_t)(8 * wid + 1) * IWP;
        float4 s = make_float4(0.f, 0.f, 0.f, 0.f);
#pragma unroll
        for (int r = 0; r < 8; ++r) {
            float4 v = *(float4*)(col + (size_t)r * IWP);
            s.x += v.x; s.y += v.y; s.z += v.z; s.w += v.w;
            *(float4*)(col + (size_t)r * IWP) = s;
        }
    }
    __syncthreads();

    // level 2: exclusive prefix of stripe totals (into O)
    if (tid < IWP) {
        float off = 0.0f;
        float* col = I + tid;
        float* ocol = O + tid;
#pragma unroll
        for (int s = 0; s < 16; ++s) {
            ocol[s * IWP] = off;
            off += col[(size_t)(8 * s + 8) * IWP];
        }
    }
    __syncthreads();

    // level 3: add stripe offsets
    for (int g = lane; g < 33; g += 32) {
        float4 o4 = *(float4*)(O + wid * IWP + 4 * g);
        float* col = I + 4 * g + (size_t)(8 * wid + 1) * IWP;
#pragma unroll
        for (int r = 0; r < 8; ++r) {
            float4 v = *(float4*)(col + (size_t)r * IWP);
            v.x += o4.x; v.y += o4.y; v.z += o4.z; v.w += o4.w;
            *(float4*)(col + (size_t)r * IWP) = v;
        }
    }
    __syncthreads();

    // ---- Phase C: warp = (f, half) ------------------------------------------
    const int f    = wid & 7;
    const int half = wid >> 3;
    const int cf   = c * FF + f;
    const float Wf = 128.0f;

    const float ym = __ldg(&ymn[cf]) * Wf;
    const float yM = __ldg(&ymx[cf]) * Wf;

    const uint32_t dbase = smem_u32(sm + D_OFF + wid * 264);
    uint32_t ga0[4], ga1[4];
    float b0[4], b1[4];
#pragma unroll
    for (int k = 0; k < 4; ++k) {
        float wv = (float)(lane + 32 * k);
        float v0 = fminf(fmaxf(wv + ym, 0.0f), Wf);
        float v1 = fminf(fmaxf(wv + yM + 1.0f, 0.0f), Wf);
        float j0f = fminf(floorf(v0), Wf - 1.0f);
        float j1f = fminf(floorf(v1), Wf - 1.0f);
        b0[k] = v0 - j0f;
        b1[k] = v1 - j1f;
        ga0[k] = dbase + 4u * (uint32_t)(int)j0f;
        ga1[k] = dbase + 4u * (uint32_t)(int)j1f;
    }

    const uint32_t Ibase = smem_u32(sm) + 16u * (uint32_t)lane;  // lane's float4 slot
    const uint32_t Ebase = smem_u32(sm) + 512u;                  // col-128 slot
    const ull M1 = pk2(-1.0f, -1.0f);
    const uint32_t dst0 = dbase + 16u * (uint32_t)lane;
    float* outc = out + ((size_t)(bc * FF + f) * HH + half * 64) * WW + lane;
    const float4* Tw = T + (f << 7) + half * 64;

    // rolling window registers
    ull r00a, r00b, r01a, r01b, r10a, r10b, r11a, r11b;
    float e00, e01, e10, e11;
    int po0, po1;

#define LOADROW(OFF, ra, rb, e)                                              \
    { float x0_, x1_, x2_, x3_;                                              \
      asm("ld.shared.v4.f32 {%0,%1,%2,%3}, [%4];"                            \
          : "=f"(x0_), "=f"(x1_), "=f"(x2_), "=f"(x3_)                       \
          : "r"(Ibase + (uint32_t)(OFF)));                                   \
      ra = pk2(x0_, x1_); rb = pk2(x2_, x3_);                                \
      asm("ld.shared.f32 %0, [%1];" : "=f"(e)                                \
          : "r"(Ebase + (uint32_t)(OFF))); }

    // prologue: full window for first h
    {
        float4 tv = Tw[0];
        po0 = __float_as_int(tv.x);
        po1 = __float_as_int(tv.y);
        LOADROW(po0,        r00a, r00b, e00);
        LOADROW(po0 + 528,  r01a, r01b, e01);
        LOADROW(po1,        r10a, r10b, e10);
        LOADROW(po1 + 528,  r11a, r11b, e11);
    }

#define ITER(SUB, SOFF)                                                      \
    {                                                                        \
        float4 tv = Tw[hh + (SUB)];                                          \
        int off0 = __float_as_int(tv.x);                                     \
        int off1 = __float_as_int(tv.y);                                     \
        float a0 = tv.z, a1 = tv.w;                                          \
        ull nq0a, nq0b, nq1a, nq1b; float ne01, ne11;                        \
        LOADROW(off0 + 528, nq0a, nq0b, ne01);                               \
        LOADROW(off1 + 528, nq1a, nq1b, ne11);                               \
        bool adv0 = (off0 != po0);                                           \
        bool adv1 = (off1 != po1);                                           \
        r00a = adv0 ? r01a : r00a;                                           \
        r00b = adv0 ? r01b : r00b;                                           \
        e00  = adv0 ? e01  : e00;                                            \
        r10a = adv1 ? r11a : r10a;                                           \
        r10b = adv1 ? r11b : r10b;                                           \
        e10  = adv1 ? e11  : e10;                                            \
        r01a = nq0a; r01b = nq0b; e01 = ne01;                                \
        r11a = nq1a; r11b = nq1b; e11 = ne11;                                \
        po0 = off0; po1 = off1;                                              \
        ull a0v = pk2(a0, a0), a1v = pk2(a1, a1);                            \
        ull g0a = ffma2(a0v, ffma2(r00a, M1, r01a), r00a);                   \
        ull g0b = ffma2(a0v, ffma2(r00b, M1, r01b), r00b);                   \
        ull g1a = ffma2(a1v, ffma2(r10a, M1, r11a), r10a);                   \
        ull g1b = ffma2(a1v, ffma2(r10b, M1, r11b), r10b);                   \
        ull da = ffma2(g0a, M1, g1a);                                        \
        ull db = ffma2(g0b, M1, g1b);                                        \
        asm volatile("st.shared.v2.u64 [%0+" #SOFF "], {%1, %2};"            \
                     :: "r"(dst0), "l"(da), "l"(db) : "memory");             \
        float ge0 = fmaf(a0, e01 - e00, e00);                                \
        float ge1 = fmaf(a1, e11 - e10, e10);                                \
        if (lane == 0)                                                       \
            asm volatile("st.shared.f32 [%0+512+" #SOFF "], %1;"             \
                         :: "r"(dbase), "f"(ge1 - ge0) : "memory");          \
        __syncwarp();                                                        \
        float* orow = outc + (size_t)(hh + (SUB)) * WW;                      \
        _Pragma("unroll")                                                    \
        for (int k = 0; k < 4; ++k) {                                        \
            float d00, d01, d10, d11;                                        \
            asm volatile("ld.shared.f32 %0, [%1+" #SOFF "];"                 \
                         : "=f"(d00) : "r"(ga0[k]));                         \
            asm volatile("ld.shared.f32 %0, [%1+4+" #SOFF "];"               \
                         : "=f"(d01) : "r"(ga0[k]));                         \
            asm volatile("ld.shared.f32 %0, [%1+" #SOFF "];"                 \
                         : "=f"(d10) : "r"(ga1[k]));                         \
            asm volatile("ld.shared.f32 %0, [%1+4+" #SOFF "];"               \
                         : "=f"(d11) : "r"(ga1[k]));                         \
            float s0 = fmaf(b0[k], d01 - d00, d00);                          \
            float s1 = fmaf(b1[k], d11 - d10, d10);                          \
            orow[32 * k] = s1 - s0;                                          \
        }                                                                    \
    }

    for (int hh = 0; hh < 64; hh += 2) {
        ITER(0, 0)
        ITER(1, 528)
    }
#undef ITER
#undef LOADROW
}

// ---------------------------------------------------------------------------
extern "C" void kernel_launch(void* const* d_in, const int* in_sizes, int n_in,
                              void* d_out, int out_size) {
    const float* input = (const float*)d_in[0];
    const float* x_min = (const float*)d_in[1];
    const float* x_max = (const float*)d_in[2];
    const float* y_min = (const float*)d_in[3];
    const float* y_max = (const float*)d_in[4];
    float* out = (float*)d_out;

    static int configured = 0;
    const int smem_bytes = SMEM_FLOATS * sizeof(float);   // 101392 B
    if (!configured) {
        cudaFuncSetAttribute(boxconv_fused,
                             cudaFuncAttributeMaxDynamicSharedMemorySize,
                             smem_bytes);
        configured = 1;
    }

    boxconv_fused<<<BB * CC, 512, smem_bytes>>>(
        input, x_min, x_max, y_min, y_max, out);
}